// round 2
// baseline (speedup 1.0000x reference)
#include <cuda_runtime.h>
#include <math.h>
#include <stdint.h>

// ---------------- scratch (device globals: allocation-free) ----------------
#define BS  4096          // B*S
#define D   1024
#define DFF 4096

__device__ float g_q  [BS * D];
__device__ float g_k  [BS * D];
__device__ float g_v  [BS * D];
__device__ float g_ctx[BS * D];
__device__ float g_t1 [BS * D];
__device__ float g_o1 [BS * D];
__device__ float g_o2 [BS * D];
__device__ float g_ff [BS * DFF];

// ---------------- tf32 helpers ---------------------------------------------
__device__ __forceinline__ uint32_t f32_to_tf32(float x) {
    uint32_t r;
    asm("cvt.rna.tf32.f32 %0, %1;" : "=r"(r) : "f"(x));
    return r;
}

__device__ __forceinline__ void mma_tf32(
    float& d0, float& d1, float& d2, float& d3,
    uint32_t a0, uint32_t a1, uint32_t a2, uint32_t a3,
    uint32_t b0, uint32_t b1)
{
    asm volatile(
        "mma.sync.aligned.m16n8k8.row.col.f32.tf32.tf32.f32 "
        "{%0,%1,%2,%3}, {%4,%5,%6,%7}, {%8,%9}, {%0,%1,%2,%3};"
        : "+f"(d0), "+f"(d1), "+f"(d2), "+f"(d3)
        : "r"(a0), "r"(a1), "r"(a2), "r"(a3), "r"(b0), "r"(b1));
}

// ---------------- GEMM: C[M,N] = A[M,K] @ B[K,N] + bias (+ReLU) -----------
// Tensor-core (tf32) GEMM with 3xTF32 split for fp32-level accuracy.
// 128x128 block tile, BK=16, 256 threads (8 warps, each 64x32).
#define APITCH 20    // 16 + 4 pad  -> conflict-free frag loads
#define BPITCH 136   // 128 + 8 pad -> conflict-free frag loads

template <bool RELU>
__global__ __launch_bounds__(256) void tf32_gemm_kernel(
    const float* __restrict__ A, const float* __restrict__ B,
    const float* __restrict__ bias, float* __restrict__ C,
    int M, int N, int K)
{
    __shared__ uint32_t As_hi[128 * APITCH];
    __shared__ uint32_t As_lo[128 * APITCH];
    __shared__ uint32_t Bs_hi[16 * BPITCH];
    __shared__ uint32_t Bs_lo[16 * BPITCH];

    const int tid  = threadIdx.x;
    const int lane = tid & 31;
    const int wid  = tid >> 5;
    const int wm   = (wid >> 2) * 64;   // warp m-offset: 0 or 64
    const int wn   = (wid & 3) * 32;    // warp n-offset: 0,32,64,96

    const int row0 = blockIdx.y * 128;
    const int col0 = blockIdx.x * 128;

    // global->smem mapping
    const int ar = tid >> 2;            // 0..63  (A rows, two passes +0/+64)
    const int ac = (tid & 3) * 4;       // 0,4,8,12
    const int br = tid >> 5;            // 0..7   (B rows, two passes +0/+8)
    const int bc = (tid & 31) * 4;      // 0..124

    float acc[4][4][4];
    #pragma unroll
    for (int mi = 0; mi < 4; mi++)
        #pragma unroll
        for (int ni = 0; ni < 4; ni++)
            #pragma unroll
            for (int r = 0; r < 4; r++) acc[mi][ni][r] = 0.f;

    for (int k0 = 0; k0 < K; k0 += 16) {
        // ---- stage A (128x16), split hi/lo ----
        #pragma unroll
        for (int rr = 0; rr < 128; rr += 64) {
            float4 v = *reinterpret_cast<const float4*>(
                A + (size_t)(row0 + ar + rr) * K + k0 + ac);
            float vv[4] = {v.x, v.y, v.z, v.w};
            #pragma unroll
            for (int j = 0; j < 4; j++) {
                uint32_t hb = f32_to_tf32(vv[j]);
                float hf = __uint_as_float(hb);
                uint32_t lb = f32_to_tf32(vv[j] - hf);
                As_hi[(ar + rr) * APITCH + ac + j] = hb;
                As_lo[(ar + rr) * APITCH + ac + j] = lb;
            }
        }
        // ---- stage B (16x128), split hi/lo ----
        #pragma unroll
        for (int rr = 0; rr < 16; rr += 8) {
            float4 v = *reinterpret_cast<const float4*>(
                B + (size_t)(k0 + br + rr) * N + col0 + bc);
            float vv[4] = {v.x, v.y, v.z, v.w};
            #pragma unroll
            for (int j = 0; j < 4; j++) {
                uint32_t hb = f32_to_tf32(vv[j]);
                float hf = __uint_as_float(hb);
                uint32_t lb = f32_to_tf32(vv[j] - hf);
                Bs_hi[(br + rr) * BPITCH + bc + j] = hb;
                Bs_lo[(br + rr) * BPITCH + bc + j] = lb;
            }
        }
        __syncthreads();

        #pragma unroll
        for (int kk = 0; kk < 16; kk += 8) {
            // fragment base indices
            const int ab = (wm + (lane >> 2)) * APITCH + kk + (lane & 3);
            const int bb = (kk + (lane & 3)) * BPITCH + wn + (lane >> 2);

            uint32_t af[4][4], bf[4][2];

            // pass 1: hi * hi
            #pragma unroll
            for (int mi = 0; mi < 4; mi++) {
                const int o = ab + mi * 16 * APITCH;
                af[mi][0] = As_hi[o];
                af[mi][1] = As_hi[o + 8 * APITCH];
                af[mi][2] = As_hi[o + 4];
                af[mi][3] = As_hi[o + 8 * APITCH + 4];
            }
            #pragma unroll
            for (int ni = 0; ni < 4; ni++) {
                const int o = bb + ni * 8;
                bf[ni][0] = Bs_hi[o];
                bf[ni][1] = Bs_hi[o + 4 * BPITCH];
            }
            #pragma unroll
            for (int mi = 0; mi < 4; mi++)
                #pragma unroll
                for (int ni = 0; ni < 4; ni++)
                    mma_tf32(acc[mi][ni][0], acc[mi][ni][1], acc[mi][ni][2], acc[mi][ni][3],
                             af[mi][0], af[mi][1], af[mi][2], af[mi][3],
                             bf[ni][0], bf[ni][1]);

            // pass 2: hi * lo
            #pragma unroll
            for (int ni = 0; ni < 4; ni++) {
                const int o = bb + ni * 8;
                bf[ni][0] = Bs_lo[o];
                bf[ni][1] = Bs_lo[o + 4 * BPITCH];
            }
            #pragma unroll
            for (int mi = 0; mi < 4; mi++)
                #pragma unroll
                for (int ni = 0; ni < 4; ni++)
                    mma_tf32(acc[mi][ni][0], acc[mi][ni][1], acc[mi][ni][2], acc[mi][ni][3],
                             af[mi][0], af[mi][1], af[mi][2], af[mi][3],
                             bf[ni][0], bf[ni][1]);

            // pass 3: lo * hi
            #pragma unroll
            for (int mi = 0; mi < 4; mi++) {
                const int o = ab + mi * 16 * APITCH;
                af[mi][0] = As_lo[o];
                af[mi][1] = As_lo[o + 8 * APITCH];
                af[mi][2] = As_lo[o + 4];
                af[mi][3] = As_lo[o + 8 * APITCH + 4];
            }
            #pragma unroll
            for (int ni = 0; ni < 4; ni++) {
                const int o = bb + ni * 8;
                bf[ni][0] = Bs_hi[o];
                bf[ni][1] = Bs_hi[o + 4 * BPITCH];
            }
            #pragma unroll
            for (int mi = 0; mi < 4; mi++)
                #pragma unroll
                for (int ni = 0; ni < 4; ni++)
                    mma_tf32(acc[mi][ni][0], acc[mi][ni][1], acc[mi][ni][2], acc[mi][ni][3],
                             af[mi][0], af[mi][1], af[mi][2], af[mi][3],
                             bf[ni][0], bf[ni][1]);
        }
        __syncthreads();
    }

    // ---- epilogue: bias (+relu), float2 stores ----
    #pragma unroll
    for (int mi = 0; mi < 4; mi++) {
        const int row = row0 + wm + mi * 16 + (lane >> 2);
        #pragma unroll
        for (int ni = 0; ni < 4; ni++) {
            const int col = col0 + wn + ni * 8 + (lane & 3) * 2;
            const float b0 = bias[col], b1 = bias[col + 1];
            float2 v0, v1;
            v0.x = acc[mi][ni][0] + b0;
            v0.y = acc[mi][ni][1] + b1;
            v1.x = acc[mi][ni][2] + b0;
            v1.y = acc[mi][ni][3] + b1;
            if (RELU) {
                v0.x = fmaxf(v0.x, 0.f); v0.y = fmaxf(v0.y, 0.f);
                v1.x = fmaxf(v1.x, 0.f); v1.y = fmaxf(v1.y, 0.f);
            }
            *reinterpret_cast<float2*>(C + (size_t)row * N + col)       = v0;
            *reinterpret_cast<float2*>(C + (size_t)(row + 8) * N + col) = v1;
        }
    }
}

// ---------------- attention (flash-lite): per (b,h), 64 q-rows / block ----
__global__ __launch_bounds__(256) void attn_kernel(
    const float* __restrict__ Q, const float* __restrict__ K,
    const float* __restrict__ V, float* __restrict__ O, int causal)
{
    __shared__ float Qs[64][65];
    __shared__ float Ks[32][65];
    __shared__ float Vs[32][65];
    __shared__ float Ps[64][33];

    const int tid = threadIdx.x;
    const int tx  = tid & 15;
    const int ty  = tid >> 4;
    const int b   = blockIdx.x >> 4;
    const int h   = blockIdx.x & 15;
    const int q0  = blockIdx.y * 64;

    const size_t base = ((size_t)b * 1024) * D + (size_t)h * 64;
    const float* Qb = Q + base + (size_t)q0 * D;

    for (int i = tid; i < 64 * 64; i += 256) {
        const int r = i >> 6, c = i & 63;
        Qs[r][c] = Qb[(size_t)r * D + c];
    }

    float mx[4], lsum[4], acc[4][4];
    #pragma unroll
    for (int i = 0; i < 4; i++) {
        mx[i] = -1e30f; lsum[i] = 0.f;
        #pragma unroll
        for (int j = 0; j < 4; j++) acc[i][j] = 0.f;
    }

    const int nkt = causal ? (q0 + 64) / 32 : 32;
    for (int jt = 0; jt < nkt; jt++) {
        const int j0 = jt * 32;
        const float* Kb = K + base + (size_t)j0 * D;
        const float* Vb = V + base + (size_t)j0 * D;
        for (int i = tid; i < 32 * 64; i += 256) {
            const int r = i >> 6, c = i & 63;
            Ks[r][c] = Kb[(size_t)r * D + c];
            Vs[r][c] = Vb[(size_t)r * D + c];
        }
        __syncthreads();

        float s[4][2];
        #pragma unroll
        for (int i = 0; i < 4; i++) { s[i][0] = 0.f; s[i][1] = 0.f; }
        #pragma unroll
        for (int kk = 0; kk < 64; kk++) {
            float qr[4];
            #pragma unroll
            for (int i = 0; i < 4; i++) qr[i] = Qs[4 * ty + i][kk];
            const float k0v = Ks[2 * tx + 0][kk];
            const float k1v = Ks[2 * tx + 1][kk];
            #pragma unroll
            for (int i = 0; i < 4; i++) {
                s[i][0] = fmaf(qr[i], k0v, s[i][0]);
                s[i][1] = fmaf(qr[i], k1v, s[i][1]);
            }
        }

        float fac[4];
        #pragma unroll
        for (int i = 0; i < 4; i++) {
            s[i][0] *= 0.125f;
            s[i][1] *= 0.125f;
            if (causal) {
                const int gq = q0 + 4 * ty + i;
                if (j0 + 2 * tx + 0 > gq) s[i][0] = -1e30f;
                if (j0 + 2 * tx + 1 > gq) s[i][1] = -1e30f;
            }
            float m = fmaxf(s[i][0], s[i][1]);
            #pragma unroll
            for (int o = 8; o > 0; o >>= 1)
                m = fmaxf(m, __shfl_xor_sync(0xffffffffu, m, o));
            const float mn = fmaxf(mx[i], m);
            fac[i] = __expf(mx[i] - mn);
            const float p0 = __expf(s[i][0] - mn);
            const float p1 = __expf(s[i][1] - mn);
            Ps[4 * ty + i][2 * tx + 0] = p0;
            Ps[4 * ty + i][2 * tx + 1] = p1;
            float rs = p0 + p1;
            #pragma unroll
            for (int o = 8; o > 0; o >>= 1)
                rs += __shfl_xor_sync(0xffffffffu, rs, o);
            lsum[i] = lsum[i] * fac[i] + rs;
            mx[i] = mn;
        }
        __syncthreads();

        #pragma unroll
        for (int i = 0; i < 4; i++)
            #pragma unroll
            for (int j = 0; j < 4; j++) acc[i][j] *= fac[i];

        #pragma unroll 8
        for (int jj = 0; jj < 32; jj++) {
            float pv[4], vv[4];
            #pragma unroll
            for (int i = 0; i < 4; i++) pv[i] = Ps[4 * ty + i][jj];
            #pragma unroll
            for (int j = 0; j < 4; j++) vv[j] = Vs[jj][4 * tx + j];
            #pragma unroll
            for (int i = 0; i < 4; i++)
                #pragma unroll
                for (int j = 0; j < 4; j++)
                    acc[i][j] = fmaf(pv[i], vv[j], acc[i][j]);
        }
        __syncthreads();
    }

    float* Ob = O + base + (size_t)q0 * D;
    #pragma unroll
    for (int i = 0; i < 4; i++) {
        const float inv = 1.f / lsum[i];
        #pragma unroll
        for (int j = 0; j < 4; j++)
            Ob[(size_t)(4 * ty + i) * D + 4 * tx + j] = acc[i][j] * inv;
    }
}

// ---------------- residual add + LayerNorm (one row per block) -------------
__device__ __forceinline__ float block_sum_256(float v, float* red)
{
    #pragma unroll
    for (int o = 16; o > 0; o >>= 1) v += __shfl_xor_sync(0xffffffffu, v, o);
    const int w = threadIdx.x >> 5;
    if ((threadIdx.x & 31) == 0) red[w] = v;
    __syncthreads();
    v = red[threadIdx.x & 7];
    #pragma unroll
    for (int o = 4; o > 0; o >>= 1) v += __shfl_xor_sync(0xffffffffu, v, o);
    __syncthreads();
    return v;
}

__global__ __launch_bounds__(256) void ln_kernel(
    const float* __restrict__ X, const float* __restrict__ Y,
    const float* __restrict__ g, const float* __restrict__ be,
    float* __restrict__ out)
{
    __shared__ float sm[D];
    __shared__ float red[8];
    const int row = blockIdx.x;
    const int tid = threadIdx.x;
    const float* x = X + (size_t)row * D;
    const float* y = Y + (size_t)row * D;

    float local = 0.f;
    #pragma unroll
    for (int i = tid; i < D; i += 256) {
        const float v = x[i] + y[i];
        sm[i] = v;
        local += v;
    }
    const float mean = block_sum_256(local, red) * (1.f / D);

    float lv = 0.f;
    #pragma unroll
    for (int i = tid; i < D; i += 256) {
        const float d = sm[i] - mean;
        lv += d * d;
    }
    const float var = block_sum_256(lv, red) * (1.f / D);
    const float rstd = rsqrtf(var + 1e-3f);

    #pragma unroll
    for (int i = tid; i < D; i += 256)
        out[(size_t)row * D + i] = (sm[i] - mean) * rstd * g[i] + be[i];
}

// ---------------- host orchestration ---------------------------------------
extern "C" void kernel_launch(void* const* d_in, const int* in_sizes, int n_in,
                              void* d_out, int out_size)
{
    const float* x   = (const float*)d_in[0];
    const float* enc = (const float*)d_in[1];

    const float *wq1, *bq1, *wk1, *bk1, *wv1, *bv1, *wo1, *bo1;
    const float *wq2, *bq2, *wk2, *bk2, *wv2, *bv2, *wo2, *bo2;
    const float *wff1, *bff1, *wff2, *bff2;
    const float *g1, *be1, *g2, *be2, *g3, *be3;

    if (in_sizes[3] == 1024) {
        wq1 = (const float*)d_in[2];  bq1 = (const float*)d_in[3];
        wk1 = (const float*)d_in[4];  bk1 = (const float*)d_in[5];
        wv1 = (const float*)d_in[6];  bv1 = (const float*)d_in[7];
        wo1 = (const float*)d_in[8];  bo1 = (const float*)d_in[9];
        wq2 = (const float*)d_in[10]; bq2 = (const float*)d_in[11];
        wk2 = (const float*)d_in[12]; bk2 = (const float*)d_in[13];
        wv2 = (const float*)d_in[14]; bv2 = (const float*)d_in[15];
        wo2 = (const float*)d_in[16]; bo2 = (const float*)d_in[17];
    } else {
        wq1 = (const float*)d_in[2];  wk1 = (const float*)d_in[3];
        wv1 = (const float*)d_in[4];  wo1 = (const float*)d_in[5];
        bq1 = (const float*)d_in[6];  bk1 = (const float*)d_in[7];
        bv1 = (const float*)d_in[8];  bo1 = (const float*)d_in[9];
        wq2 = (const float*)d_in[10]; wk2 = (const float*)d_in[11];
        wv2 = (const float*)d_in[12]; wo2 = (const float*)d_in[13];
        bq2 = (const float*)d_in[14]; bk2 = (const float*)d_in[15];
        bv2 = (const float*)d_in[16]; bo2 = (const float*)d_in[17];
    }
    wff1 = (const float*)d_in[18]; bff1 = (const float*)d_in[19];
    wff2 = (const float*)d_in[20]; bff2 = (const float*)d_in[21];
    g1 = (const float*)d_in[22]; be1 = (const float*)d_in[23];
    g2 = (const float*)d_in[24]; be2 = (const float*)d_in[25];
    g3 = (const float*)d_in[26]; be3 = (const float*)d_in[27];

    float *q, *k, *v, *ctx, *t1, *o1, *o2, *ff;
    cudaGetSymbolAddress((void**)&q,   g_q);
    cudaGetSymbolAddress((void**)&k,   g_k);
    cudaGetSymbolAddress((void**)&v,   g_v);
    cudaGetSymbolAddress((void**)&ctx, g_ctx);
    cudaGetSymbolAddress((void**)&t1,  g_t1);
    cudaGetSymbolAddress((void**)&o1,  g_o1);
    cudaGetSymbolAddress((void**)&o2,  g_o2);
    cudaGetSymbolAddress((void**)&ff,  g_ff);

    const dim3 gD(D / 128, BS / 128);       // N=1024 GEMMs
    const dim3 gF1(DFF / 128, BS / 128);    // N=4096 GEMM
    const dim3 gAttn(64, 16);               // (B*H, S/64)

    // ---- self-attention block (causal) ----
    tf32_gemm_kernel<false><<<gD, 256>>>(x, wq1, bq1, q, BS, D, D);
    tf32_gemm_kernel<false><<<gD, 256>>>(x, wk1, bk1, k, BS, D, D);
    tf32_gemm_kernel<false><<<gD, 256>>>(x, wv1, bv1, v, BS, D, D);
    attn_kernel<<<gAttn, 256>>>(q, k, v, ctx, 1);
    tf32_gemm_kernel<false><<<gD, 256>>>(ctx, wo1, bo1, t1, BS, D, D);
    ln_kernel<<<BS, 256>>>(x, t1, g1, be1, o1);

    // ---- cross-attention block ----
    tf32_gemm_kernel<false><<<gD, 256>>>(o1,  wq2, bq2, q, BS, D, D);
    tf32_gemm_kernel<false><<<gD, 256>>>(enc, wk2, bk2, k, BS, D, D);
    tf32_gemm_kernel<false><<<gD, 256>>>(enc, wv2, bv2, v, BS, D, D);
    attn_kernel<<<gAttn, 256>>>(q, k, v, ctx, 0);
    tf32_gemm_kernel<false><<<gD, 256>>>(ctx, wo2, bo2, t1, BS, D, D);
    ln_kernel<<<BS, 256>>>(o1, t1, g2, be2, o2);

    // ---- FFN block ----
    tf32_gemm_kernel<true ><<<gF1, 256>>>(o2, wff1, bff1, ff, BS, DFF, D);
    tf32_gemm_kernel<false><<<gD, 256>>>(ff, wff2, bff2, t1, BS, D, DFF);
    ln_kernel<<<BS, 256>>>(o2, t1, g3, be3, (float*)d_out);

    (void)n_in; (void)out_size;
}

// round 4
// speedup vs baseline: 1.2079x; 1.2079x over previous
#include <cuda_runtime.h>
#include <math.h>
#include <stdint.h>

// ---------------- scratch (device globals: allocation-free) ----------------
#define BS  4096          // B*S
#define D   1024
#define DFF 4096

__device__ float g_q  [BS * D];
__device__ float g_k  [BS * D];
__device__ float g_v  [BS * D];
__device__ float g_ctx[BS * D];
__device__ float g_t1 [BS * D];
__device__ float g_o1 [BS * D];
__device__ float g_o2 [BS * D];
__device__ float g_ff [BS * DFF];

// ---------------- helpers ---------------------------------------------------
__device__ __forceinline__ uint32_t smem_u32(const void* p) {
    uint32_t a;
    asm("{ .reg .u64 t; cvta.to.shared.u64 t, %1; cvt.u32.u64 %0, t; }"
        : "=r"(a) : "l"(p));
    return a;
}

// pack bf16x2: low half = bf16(x0), high half = bf16(x1)
__device__ __forceinline__ uint32_t cvt2_bf16(float x1, float x0) {
    uint32_t r;
    asm("cvt.rn.bf16x2.f32 %0, %1, %2;" : "=r"(r) : "f"(x1), "f"(x0));
    return r;
}

// split (x0,x1) into packed hi word and packed lo word (lo = x - bf16(x))
__device__ __forceinline__ void split2(float x0, float x1,
                                       uint32_t& h, uint32_t& l) {
    h = cvt2_bf16(x1, x0);
    const float h0 = __uint_as_float(h << 16);
    const float h1 = __uint_as_float(h & 0xffff0000u);
    l = cvt2_bf16(x1 - h1, x0 - h0);
}

__device__ __forceinline__ void ldsm_x4(uint32_t* r, uint32_t addr) {
    asm volatile("ldmatrix.sync.aligned.m8n8.x4.shared.b16 {%0,%1,%2,%3}, [%4];"
                 : "=r"(r[0]), "=r"(r[1]), "=r"(r[2]), "=r"(r[3]) : "r"(addr));
}
__device__ __forceinline__ void ldsm_x4_t(uint32_t* r, uint32_t addr) {
    asm volatile("ldmatrix.sync.aligned.m8n8.x4.trans.shared.b16 {%0,%1,%2,%3}, [%4];"
                 : "=r"(r[0]), "=r"(r[1]), "=r"(r[2]), "=r"(r[3]) : "r"(addr));
}

__device__ __forceinline__ void mma_bf16(float* d, const uint32_t* a,
                                         const uint32_t* b) {
    asm volatile(
        "mma.sync.aligned.m16n8k16.row.col.f32.bf16.bf16.f32 "
        "{%0,%1,%2,%3}, {%4,%5,%6,%7}, {%8,%9}, {%0,%1,%2,%3};"
        : "+f"(d[0]), "+f"(d[1]), "+f"(d[2]), "+f"(d[3])
        : "r"(a[0]), "r"(a[1]), "r"(a[2]), "r"(a[3]), "r"(b[0]), "r"(b[1]));
}

// ---------------- split-bf16 GEMM: C = A@B + bias (+ReLU) -------------------
// 128x128 CTA tile, 16 f32 K per stage -> 48 virtual bf16 K'.
// A smem: [128 rows][56 bf16]  (blocks: hiA[16] | loA[16] | hiA[16]), pitch 28 words
// B smem: [48 rows k'][136 bf16] (rows 0-15 hiB, 16-31 hiB, 32-47 loB), pitch 68 words
#define BKF        16
#define APITCH_W   28
#define BPITCH_W   68
#define A_STAGE_W  (128 * APITCH_W)                 // 3584 words
#define B_STAGE_W  (48 * BPITCH_W)                  // 3264 words
#define STAGE_W    (A_STAGE_W + B_STAGE_W)          // 6848 words
#define GEMM_SMEM_BYTES (2 * STAGE_W * 4)           // 54784 B

__device__ __forceinline__ void store_stage(
    uint32_t* Asb, uint32_t* Bsb, int aw, int bw,
    float4 a0, float4 a1, float4 b0, float4 b1)
{
    uint32_t h[4], l[4];
    split2(a0.x, a0.y, h[0], l[0]);
    split2(a0.z, a0.w, h[1], l[1]);
    split2(a1.x, a1.y, h[2], l[2]);
    split2(a1.z, a1.w, h[3], l[3]);
    uint4 H = make_uint4(h[0], h[1], h[2], h[3]);
    uint4 L = make_uint4(l[0], l[1], l[2], l[3]);
    *reinterpret_cast<uint4*>(Asb + aw)      = H;
    *reinterpret_cast<uint4*>(Asb + aw + 8)  = L;
    *reinterpret_cast<uint4*>(Asb + aw + 16) = H;

    split2(b0.x, b0.y, h[0], l[0]);
    split2(b0.z, b0.w, h[1], l[1]);
    split2(b1.x, b1.y, h[2], l[2]);
    split2(b1.z, b1.w, h[3], l[3]);
    H = make_uint4(h[0], h[1], h[2], h[3]);
    L = make_uint4(l[0], l[1], l[2], l[3]);
    *reinterpret_cast<uint4*>(Bsb + bw)                   = H;
    *reinterpret_cast<uint4*>(Bsb + bw + 16 * BPITCH_W)   = H;
    *reinterpret_cast<uint4*>(Bsb + bw + 32 * BPITCH_W)   = L;
}

template <bool RELU>
__global__ __launch_bounds__(256, 2) void bf16_gemm_kernel(
    const float* __restrict__ A, const float* __restrict__ B,
    const float* __restrict__ bias, float* __restrict__ C,
    int M, int N, int K)
{
    extern __shared__ uint32_t sw[];
    const int tid  = threadIdx.x;
    const int lane = tid & 31;
    const int wid  = tid >> 5;
    const int wm   = (wid >> 2) * 64;
    const int wn   = (wid & 3) * 32;
    const int row0 = blockIdx.y * 128;
    const int col0 = blockIdx.x * 128;

    // global load mapping
    const int arow = tid >> 1;
    const int akk  = (tid & 1) * 8;
    const int bkk  = tid >> 4;
    const int bnn  = (tid & 15) * 8;
    const float* aP = A + (size_t)(row0 + arow) * K + akk;
    const float* bP = B + (size_t)bkk * N + col0 + bnn;

    // smem store word offsets (within a stage)
    const int aw = arow * APITCH_W + (akk >> 1);
    const int bw = bkk * BPITCH_W + (bnn >> 1);

    uint32_t* As[2] = { sw,             sw + STAGE_W };
    uint32_t* Bs[2] = { sw + A_STAGE_W, sw + STAGE_W + A_STAGE_W };

    const uint32_t sb = smem_u32(sw);
    const uint32_t abase0 = sb;
    const uint32_t bbase0 = sb + A_STAGE_W * 4;

    // ldmatrix per-thread bases (word offsets)
    const int a_ld_row = wm + (lane & 15);
    const int a_ld_cw  = (lane >> 4) * 4;
    const int b_ld_row = (lane & 7) + ((lane >> 3) & 1) * 8;
    const int b_ld_cw  = (wn >> 1) + (lane >> 4) * 4;

    float acc[4][4][4];
    #pragma unroll
    for (int mi = 0; mi < 4; mi++)
        #pragma unroll
        for (int ni = 0; ni < 4; ni++)
            #pragma unroll
            for (int r = 0; r < 4; r++) acc[mi][ni][r] = 0.f;

    const int NS = K / BKF;

    // prologue: stage 0
    {
        float4 a0 = *reinterpret_cast<const float4*>(aP);
        float4 a1 = *reinterpret_cast<const float4*>(aP + 4);
        float4 b0 = *reinterpret_cast<const float4*>(bP);
        float4 b1 = *reinterpret_cast<const float4*>(bP + 4);
        store_stage(As[0], Bs[0], aw, bw, a0, a1, b0, b1);
    }
    __syncthreads();

    for (int s = 0; s < NS; s++) {
        const int buf = s & 1;

        float4 pa0, pa1, pb0, pb1;
        if (s + 1 < NS) {
            const float* ap = aP + (s + 1) * BKF;
            const float* bp = bP + (size_t)(s + 1) * BKF * N;
            pa0 = *reinterpret_cast<const float4*>(ap);
            pa1 = *reinterpret_cast<const float4*>(ap + 4);
            pb0 = *reinterpret_cast<const float4*>(bp);
            pb1 = *reinterpret_cast<const float4*>(bp + 4);
        }

        const uint32_t abase = abase0 + buf * (STAGE_W * 4);
        const uint32_t bbase = bbase0 + buf * (STAGE_W * 4);

        #pragma unroll
        for (int ks = 0; ks < 3; ks++) {
            uint32_t a[4][4], bfr[2][4];
            #pragma unroll
            for (int mi = 0; mi < 4; mi++)
                ldsm_x4(a[mi], abase +
                    ((a_ld_row + mi * 16) * APITCH_W + ks * 8 + a_ld_cw) * 4);
            #pragma unroll
            for (int nj = 0; nj < 2; nj++)
                ldsm_x4_t(bfr[nj], bbase +
                    ((b_ld_row + ks * 16) * BPITCH_W + b_ld_cw + nj * 8) * 4);
            #pragma unroll
            for (int mi = 0; mi < 4; mi++)
                #pragma unroll
                for (int ni = 0; ni < 4; ni++)
                    mma_bf16(acc[mi][ni], a[mi], &bfr[ni >> 1][(ni & 1) * 2]);
        }

        if (s + 1 < NS)
            store_stage(As[buf ^ 1], Bs[buf ^ 1], aw, bw, pa0, pa1, pb0, pb1);
        __syncthreads();
    }

    // epilogue: regs -> gmem with bias (+relu)
    #pragma unroll
    for (int mi = 0; mi < 4; mi++) {
        const int row = row0 + wm + mi * 16 + (lane >> 2);
        #pragma unroll
        for (int ni = 0; ni < 4; ni++) {
            const int col = col0 + wn + ni * 8 + (lane & 3) * 2;
            const float b0v = bias[col], b1v = bias[col + 1];
            float2 v0, v1;
            v0.x = acc[mi][ni][0] + b0v;
            v0.y = acc[mi][ni][1] + b1v;
            v1.x = acc[mi][ni][2] + b0v;
            v1.y = acc[mi][ni][3] + b1v;
            if (RELU) {
                v0.x = fmaxf(v0.x, 0.f); v0.y = fmaxf(v0.y, 0.f);
                v1.x = fmaxf(v1.x, 0.f); v1.y = fmaxf(v1.y, 0.f);
            }
            *reinterpret_cast<float2*>(C + (size_t)row * N + col)       = v0;
            *reinterpret_cast<float2*>(C + (size_t)(row + 8) * N + col) = v1;
        }
    }
}

// ---------------- attention (flash-lite): per (b,h), 64 q-rows / block ----
__global__ __launch_bounds__(256) void attn_kernel(
    const float* __restrict__ Q, const float* __restrict__ K,
    const float* __restrict__ V, float* __restrict__ O, int causal)
{
    __shared__ float Qs[64][65];
    __shared__ float Ks[32][65];
    __shared__ float Vs[32][65];
    __shared__ float Ps[64][33];

    const int tid = threadIdx.x;
    const int tx  = tid & 15;
    const int ty  = tid >> 4;
    const int b   = blockIdx.x >> 4;
    const int h   = blockIdx.x & 15;
    const int q0  = blockIdx.y * 64;

    const size_t base = ((size_t)b * 1024) * D + (size_t)h * 64;
    const float* Qb = Q + base + (size_t)q0 * D;

    for (int i = tid; i < 64 * 64; i += 256) {
        const int r = i >> 6, c = i & 63;
        Qs[r][c] = Qb[(size_t)r * D + c];
    }

    float mx[4], lsum[4], acc[4][4];
    #pragma unroll
    for (int i = 0; i < 4; i++) {
        mx[i] = -1e30f; lsum[i] = 0.f;
        #pragma unroll
        for (int j = 0; j < 4; j++) acc[i][j] = 0.f;
    }

    const int nkt = causal ? (q0 + 64) / 32 : 32;
    for (int jt = 0; jt < nkt; jt++) {
        const int j0 = jt * 32;
        const float* Kb = K + base + (size_t)j0 * D;
        const float* Vb = V + base + (size_t)j0 * D;
        for (int i = tid; i < 32 * 64; i += 256) {
            const int r = i >> 6, c = i & 63;
            Ks[r][c] = Kb[(size_t)r * D + c];
            Vs[r][c] = Vb[(size_t)r * D + c];
        }
        __syncthreads();

        float s[4][2];
        #pragma unroll
        for (int i = 0; i < 4; i++) { s[i][0] = 0.f; s[i][1] = 0.f; }
        #pragma unroll
        for (int kk = 0; kk < 64; kk++) {
            float qr[4];
            #pragma unroll
            for (int i = 0; i < 4; i++) qr[i] = Qs[4 * ty + i][kk];
            const float k0v = Ks[2 * tx + 0][kk];
            const float k1v = Ks[2 * tx + 1][kk];
            #pragma unroll
            for (int i = 0; i < 4; i++) {
                s[i][0] = fmaf(qr[i], k0v, s[i][0]);
                s[i][1] = fmaf(qr[i], k1v, s[i][1]);
            }
        }

        float fac[4];
        #pragma unroll
        for (int i = 0; i < 4; i++) {
            s[i][0] *= 0.125f;
            s[i][1] *= 0.125f;
            if (causal) {
                const int gq = q0 + 4 * ty + i;
                if (j0 + 2 * tx + 0 > gq) s[i][0] = -1e30f;
                if (j0 + 2 * tx + 1 > gq) s[i][1] = -1e30f;
            }
            float m = fmaxf(s[i][0], s[i][1]);
            #pragma unroll
            for (int o = 8; o > 0; o >>= 1)
                m = fmaxf(m, __shfl_xor_sync(0xffffffffu, m, o));
            const float mn = fmaxf(mx[i], m);
            fac[i] = __expf(mx[i] - mn);
            const float p0 = __expf(s[i][0] - mn);
            const float p1 = __expf(s[i][1] - mn);
            Ps[4 * ty + i][2 * tx + 0] = p0;
            Ps[4 * ty + i][2 * tx + 1] = p1;
            float rs = p0 + p1;
            #pragma unroll
            for (int o = 8; o > 0; o >>= 1)
                rs += __shfl_xor_sync(0xffffffffu, rs, o);
            lsum[i] = lsum[i] * fac[i] + rs;
            mx[i] = mn;
        }
        __syncthreads();

        #pragma unroll
        for (int i = 0; i < 4; i++)
            #pragma unroll
            for (int j = 0; j < 4; j++) acc[i][j] *= fac[i];

        #pragma unroll 8
        for (int jj = 0; jj < 32; jj++) {
            float pv[4], vv[4];
            #pragma unroll
            for (int i = 0; i < 4; i++) pv[i] = Ps[4 * ty + i][jj];
            #pragma unroll
            for (int j = 0; j < 4; j++) vv[j] = Vs[jj][4 * tx + j];
            #pragma unroll
            for (int i = 0; i < 4; i++)
                #pragma unroll
                for (int j = 0; j < 4; j++)
                    acc[i][j] = fmaf(pv[i], vv[j], acc[i][j]);
        }
        __syncthreads();
    }

    float* Ob = O + base + (size_t)q0 * D;
    #pragma unroll
    for (int i = 0; i < 4; i++) {
        const float inv = 1.f / lsum[i];
        #pragma unroll
        for (int j = 0; j < 4; j++)
            Ob[(size_t)(4 * ty + i) * D + 4 * tx + j] = acc[i][j] * inv;
    }
}

// ---------------- residual add + LayerNorm (one row per block) -------------
__device__ __forceinline__ float block_sum_256(float v, float* red)
{
    #pragma unroll
    for (int o = 16; o > 0; o >>= 1) v += __shfl_xor_sync(0xffffffffu, v, o);
    const int w = threadIdx.x >> 5;
    if ((threadIdx.x & 31) == 0) red[w] = v;
    __syncthreads();
    v = red[threadIdx.x & 7];
    #pragma unroll
    for (int o = 4; o > 0; o >>= 1) v += __shfl_xor_sync(0xffffffffu, v, o);
    __syncthreads();
    return v;
}

__global__ __launch_bounds__(256) void ln_kernel(
    const float* __restrict__ X, const float* __restrict__ Y,
    const float* __restrict__ g, const float* __restrict__ be,
    float* __restrict__ out)
{
    __shared__ float sm[D];
    __shared__ float red[8];
    const int row = blockIdx.x;
    const int tid = threadIdx.x;
    const float* x = X + (size_t)row * D;
    const float* y = Y + (size_t)row * D;

    float local = 0.f;
    #pragma unroll
    for (int i = tid; i < D; i += 256) {
        const float v = x[i] + y[i];
        sm[i] = v;
        local += v;
    }
    const float mean = block_sum_256(local, red) * (1.f / D);

    float lv = 0.f;
    #pragma unroll
    for (int i = tid; i < D; i += 256) {
        const float d = sm[i] - mean;
        lv += d * d;
    }
    const float var = block_sum_256(lv, red) * (1.f / D);
    const float rstd = rsqrtf(var + 1e-3f);

    #pragma unroll
    for (int i = tid; i < D; i += 256)
        out[(size_t)row * D + i] = (sm[i] - mean) * rstd * g[i] + be[i];
}

// ---------------- host orchestration ---------------------------------------
extern "C" void kernel_launch(void* const* d_in, const int* in_sizes, int n_in,
                              void* d_out, int out_size)
{
    const float* x   = (const float*)d_in[0];
    const float* enc = (const float*)d_in[1];

    const float *wq1, *bq1, *wk1, *bk1, *wv1, *bv1, *wo1, *bo1;
    const float *wq2, *bq2, *wk2, *bk2, *wv2, *bv2, *wo2, *bo2;
    const float *wff1, *bff1, *wff2, *bff2;
    const float *g1, *be1, *g2, *be2, *g3, *be3;

    if (in_sizes[3] == 1024) {
        wq1 = (const float*)d_in[2];  bq1 = (const float*)d_in[3];
        wk1 = (const float*)d_in[4];  bk1 = (const float*)d_in[5];
        wv1 = (const float*)d_in[6];  bv1 = (const float*)d_in[7];
        wo1 = (const float*)d_in[8];  bo1 = (const float*)d_in[9];
        wq2 = (const float*)d_in[10]; bq2 = (const float*)d_in[11];
        wk2 = (const float*)d_in[12]; bk2 = (const float*)d_in[13];
        wv2 = (const float*)d_in[14]; bv2 = (const float*)d_in[15];
        wo2 = (const float*)d_in[16]; bo2 = (const float*)d_in[17];
    } else {
        wq1 = (const float*)d_in[2];  wk1 = (const float*)d_in[3];
        wv1 = (const float*)d_in[4];  wo1 = (const float*)d_in[5];
        bq1 = (const float*)d_in[6];  bk1 = (const float*)d_in[7];
        bv1 = (const float*)d_in[8];  bo1 = (const float*)d_in[9];
        wq2 = (const float*)d_in[10]; wk2 = (const float*)d_in[11];
        wv2 = (const float*)d_in[12]; wo2 = (const float*)d_in[13];
        bq2 = (const float*)d_in[14]; bk2 = (const float*)d_in[15];
        bv2 = (const float*)d_in[16]; bo2 = (const float*)d_in[17];
    }
    wff1 = (const float*)d_in[18]; bff1 = (const float*)d_in[19];
    wff2 = (const float*)d_in[20]; bff2 = (const float*)d_in[21];
    g1 = (const float*)d_in[22]; be1 = (const float*)d_in[23];
    g2 = (const float*)d_in[24]; be2 = (const float*)d_in[25];
    g3 = (const float*)d_in[26]; be3 = (const float*)d_in[27];

    float *q, *k, *v, *ctx, *t1, *o1, *o2, *ff;
    cudaGetSymbolAddress((void**)&q,   g_q);
    cudaGetSymbolAddress((void**)&k,   g_k);
    cudaGetSymbolAddress((void**)&v,   g_v);
    cudaGetSymbolAddress((void**)&ctx, g_ctx);
    cudaGetSymbolAddress((void**)&t1,  g_t1);
    cudaGetSymbolAddress((void**)&o1,  g_o1);
    cudaGetSymbolAddress((void**)&o2,  g_o2);
    cudaGetSymbolAddress((void**)&ff,  g_ff);

    cudaFuncSetAttribute(bf16_gemm_kernel<false>,
        cudaFuncAttributeMaxDynamicSharedMemorySize, GEMM_SMEM_BYTES);
    cudaFuncSetAttribute(bf16_gemm_kernel<true>,
        cudaFuncAttributeMaxDynamicSharedMemorySize, GEMM_SMEM_BYTES);

    const dim3 gD(D / 128, BS / 128);       // N=1024 GEMMs
    const dim3 gF1(DFF / 128, BS / 128);    // N=4096 GEMM
    const dim3 gAttn(64, 16);               // (B*H, S/64)
    const int SM = GEMM_SMEM_BYTES;

    // ---- self-attention block (causal) ----
    bf16_gemm_kernel<false><<<gD, 256, SM>>>(x, wq1, bq1, q, BS, D, D);
    bf16_gemm_kernel<false><<<gD, 256, SM>>>(x, wk1, bk1, k, BS, D, D);
    bf16_gemm_kernel<false><<<gD, 256, SM>>>(x, wv1, bv1, v, BS, D, D);
    attn_kernel<<<gAttn, 256>>>(q, k, v, ctx, 1);
    bf16_gemm_kernel<false><<<gD, 256, SM>>>(ctx, wo1, bo1, t1, BS, D, D);
    ln_kernel<<<BS, 256>>>(x, t1, g1, be1, o1);

    // ---- cross-attention block ----
    bf16_gemm_kernel<false><<<gD, 256, SM>>>(o1,  wq2, bq2, q, BS, D, D);
    bf16_gemm_kernel<false><<<gD, 256, SM>>>(enc, wk2, bk2, k, BS, D, D);
    bf16_gemm_kernel<false><<<gD, 256, SM>>>(enc, wv2, bv2, v, BS, D, D);
    attn_kernel<<<gAttn, 256>>>(q, k, v, ctx, 0);
    bf16_gemm_kernel<false><<<gD, 256, SM>>>(ctx, wo2, bo2, t1, BS, D, D);
    ln_kernel<<<BS, 256>>>(o1, t1, g2, be2, o2);

    // ---- FFN block ----
    bf16_gemm_kernel<true ><<<gF1, 256, SM>>>(o2, wff1, bff1, ff, BS, DFF, D);
    bf16_gemm_kernel<false><<<gD, 256, SM>>>(ff, wff2, bff2, t1, BS, D, DFF);
    ln_kernel<<<BS, 256>>>(o2, t1, g3, be3, (float*)d_out);

    (void)n_in; (void)out_size;
}

// round 12
// speedup vs baseline: 1.9173x; 1.5872x over previous
#include <cuda_runtime.h>
#include <math.h>
#include <stdint.h>

// ---------------- scratch (device globals: allocation-free) ----------------
#define BS  4096          // B*S
#define D   1024
#define DFF 4096

__device__ float g_q  [BS * D];
__device__ float g_k  [BS * D];
__device__ float g_v  [BS * D];
__device__ float g_ctx[BS * D];
__device__ float g_t1 [BS * D];
__device__ float g_o1 [BS * D];
__device__ float g_o2 [BS * D];
__device__ float g_ff [BS * DFF];

// split-bf16 operand buffers: A' = [hi | lo | hi] (M x 3K), B' = [hi; hi; lo] (3K x N)
__device__ uint16_t g_x3  [BS * 3 * D];
__device__ uint16_t g_enc3[BS * 3 * D];
__device__ uint16_t g_o13 [BS * 3 * D];
__device__ uint16_t g_o23 [BS * 3 * D];
__device__ uint16_t g_ctx3[BS * 3 * D];
__device__ uint16_t g_ff3 [BS * 3 * DFF];
__device__ uint16_t g_w3  [8][3 * D * D];    // wq1,wk1,wv1,wo1,wq2,wk2,wv2,wo2
__device__ uint16_t g_wf13[3 * D * DFF];
__device__ uint16_t g_wf23[3 * DFF * D];

// ---------------- helpers ---------------------------------------------------
__device__ __forceinline__ uint32_t smem_u32(const void* p) {
    uint32_t a;
    asm("{ .reg .u64 t; cvta.to.shared.u64 t, %1; cvt.u32.u64 %0, t; }"
        : "=r"(a) : "l"(p));
    return a;
}

__device__ __forceinline__ uint32_t cvt2_bf16(float x1, float x0) {
    uint32_t r;
    asm("cvt.rn.bf16x2.f32 %0, %1, %2;" : "=r"(r) : "f"(x1), "f"(x0));
    return r;
}

__device__ __forceinline__ void split2(float x0, float x1,
                                       uint32_t& h, uint32_t& l) {
    h = cvt2_bf16(x1, x0);
    const float h0 = __uint_as_float(h << 16);
    const float h1 = __uint_as_float(h & 0xffff0000u);
    l = cvt2_bf16(x1 - h1, x0 - h0);
}

__device__ __forceinline__ void ldsm_x4(uint32_t* r, uint32_t addr) {
    asm volatile("ldmatrix.sync.aligned.m8n8.x4.shared.b16 {%0,%1,%2,%3}, [%4];"
                 : "=r"(r[0]), "=r"(r[1]), "=r"(r[2]), "=r"(r[3]) : "r"(addr));
}
__device__ __forceinline__ void ldsm_x4_t(uint32_t* r, uint32_t addr) {
    asm volatile("ldmatrix.sync.aligned.m8n8.x4.trans.shared.b16 {%0,%1,%2,%3}, [%4];"
                 : "=r"(r[0]), "=r"(r[1]), "=r"(r[2]), "=r"(r[3]) : "r"(addr));
}

__device__ __forceinline__ void mma_bf16(float* d, const uint32_t* a,
                                         const uint32_t* b) {
    asm volatile(
        "mma.sync.aligned.m16n8k16.row.col.f32.bf16.bf16.f32 "
        "{%0,%1,%2,%3}, {%4,%5,%6,%7}, {%8,%9}, {%0,%1,%2,%3};"
        : "+f"(d[0]), "+f"(d[1]), "+f"(d[2]), "+f"(d[3])
        : "r"(a[0]), "r"(a[1]), "r"(a[2]), "r"(a[3]), "r"(b[0]), "r"(b[1]));
}

__device__ __forceinline__ void cp16(uint32_t dst, const void* src) {
    asm volatile("cp.async.cg.shared.global [%0], [%1], 16;"
                 :: "r"(dst), "l"(src));
}
#define CP_COMMIT() asm volatile("cp.async.commit_group;")

// ---------------- split kernels ---------------------------------------------
// A': out[m, k]=hi, out[m, K+k]=lo, out[m, 2K+k]=hi     (out is [M, 3K] bf16)
__global__ void split_a_kernel(const float* __restrict__ in,
                               uint16_t* __restrict__ out, int K, int total4)
{
    const int idx = blockIdx.x * blockDim.x + threadIdx.x;
    if (idx >= total4) return;
    const float4 v = reinterpret_cast<const float4*>(in)[idx];
    uint32_t h0, l0, h1, l1;
    split2(v.x, v.y, h0, l0);
    split2(v.z, v.w, h1, l1);
    const int e = idx * 4;
    const int m = e / K, k = e % K;
    uint16_t* rp = out + (size_t)m * 3 * K;
    const uint2 H = make_uint2(h0, h1), L = make_uint2(l0, l1);
    *reinterpret_cast<uint2*>(rp + k)         = H;
    *reinterpret_cast<uint2*>(rp + 2 * K + k) = H;
    *reinterpret_cast<uint2*>(rp + K + k)     = L;
}

// B': out[k, n]=hi, out[K+k, n]=hi, out[2K+k, n]=lo     (out is [3K, N] bf16)
__global__ void split_b_kernel(const float* __restrict__ in,
                               uint16_t* __restrict__ out, int K, int N,
                               int total4)
{
    const int idx = blockIdx.x * blockDim.x + threadIdx.x;
    if (idx >= total4) return;
    const float4 v = reinterpret_cast<const float4*>(in)[idx];
    uint32_t h0, l0, h1, l1;
    split2(v.x, v.y, h0, l0);
    split2(v.z, v.w, h1, l1);
    const int e = idx * 4;
    const int k = e / N, n = e % N;
    const uint2 H = make_uint2(h0, h1), L = make_uint2(l0, l1);
    *reinterpret_cast<uint2*>(out + (size_t)k * N + n)           = H;
    *reinterpret_cast<uint2*>(out + (size_t)(K + k) * N + n)     = H;
    *reinterpret_cast<uint2*>(out + (size_t)(2 * K + k) * N + n) = L;
}

// ---------------- bf16 GEMM: C[M,N] = A'[M,K3] @ B'[K3,N] + bias (+ReLU) ---
// 128x128 CTA tile, BK=32 bf16, cp.async 3-stage ring, 8 warps (64x32 each).
// A smem rows: 32 bf16 data @ pitch 80B; B rows: 128 bf16 data @ pitch 272B.
#define A_STG_B 10240                     // 128 * 80
#define B_STG_B 8704                      // 32 * 272
#define STG_B   (A_STG_B + B_STG_B)       // 18944
#define GEMM_SMEM_BYTES (3 * STG_B)       // 56832

template <bool RELU>
__global__ __launch_bounds__(256, 2) void bf16s_gemm_kernel(
    const uint16_t* __restrict__ A3, const uint16_t* __restrict__ B3,
    const float* __restrict__ bias, float* __restrict__ C,
    int M, int N, int K3)
{
    extern __shared__ char smem[];
    const uint32_t sb = smem_u32(smem);
    const int tid  = threadIdx.x;
    const int lane = tid & 31;
    const int wid  = tid >> 5;
    const int wm   = (wid >> 2) * 64;
    const int wn   = (wid & 3) * 32;
    const int row0 = blockIdx.y * 128;
    const int col0 = blockIdx.x * 128;
    const int NS   = K3 >> 5;

    const int a_r  = tid >> 2, a_sg = tid & 3;     // + 64 rows on pass 1
    const int b_r  = tid >> 4, b_sg = tid & 15;    // + 16 rows on pass 1

    float acc[4][4][4];
    #pragma unroll
    for (int mi = 0; mi < 4; mi++)
        #pragma unroll
        for (int ni = 0; ni < 4; ni++)
            #pragma unroll
            for (int r = 0; r < 4; r++) acc[mi][ni][r] = 0.f;

    #define ISSUE_STAGE(s) do {                                               \
        const uint32_t _b = sb + ((s) % 3) * STG_B;                           \
        const int _k0 = (s) * 32;                                             \
        cp16(_b + a_r * 80 + a_sg * 16,                                       \
             A3 + (size_t)(row0 + a_r) * K3 + _k0 + a_sg * 8);                \
        cp16(_b + (a_r + 64) * 80 + a_sg * 16,                                \
             A3 + (size_t)(row0 + a_r + 64) * K3 + _k0 + a_sg * 8);           \
        cp16(_b + A_STG_B + b_r * 272 + b_sg * 16,                            \
             B3 + (size_t)(_k0 + b_r) * N + col0 + b_sg * 8);                 \
        cp16(_b + A_STG_B + (b_r + 16) * 272 + b_sg * 16,                     \
             B3 + (size_t)(_k0 + b_r + 16) * N + col0 + b_sg * 8);            \
        CP_COMMIT();                                                          \
    } while (0)

    ISSUE_STAGE(0);
    ISSUE_STAGE(1);

    for (int s = 0; s < NS; s++) {
        if (s < NS - 1) asm volatile("cp.async.wait_group 1;" ::: "memory");
        else            asm volatile("cp.async.wait_group 0;" ::: "memory");
        __syncthreads();
        if (s + 2 < NS) ISSUE_STAGE(s + 2);

        const uint32_t base = sb + (s % 3) * STG_B;
        const uint32_t ab = base, bb = base + A_STG_B;

        #pragma unroll
        for (int ks = 0; ks < 2; ks++) {
            uint32_t a[4][4], bfr[2][4];
            #pragma unroll
            for (int mi = 0; mi < 4; mi++)
                ldsm_x4(a[mi], ab + (wm + (lane & 15) + mi * 16) * 80
                                  + ks * 32 + (lane >> 4) * 16);
            #pragma unroll
            for (int nj = 0; nj < 2; nj++)
                ldsm_x4_t(bfr[nj], bb + ((lane & 7) + ((lane >> 3) & 1) * 8
                                         + ks * 16) * 272
                                      + wn * 2 + (lane >> 4) * 16 + nj * 32);
            #pragma unroll
            for (int mi = 0; mi < 4; mi++)
                #pragma unroll
                for (int ni = 0; ni < 4; ni++)
                    mma_bf16(acc[mi][ni], a[mi], &bfr[ni >> 1][(ni & 1) * 2]);
        }
    }
    #undef ISSUE_STAGE

    // epilogue: regs -> gmem with bias (+relu)
    #pragma unroll
    for (int mi = 0; mi < 4; mi++) {
        const int row = row0 + wm + mi * 16 + (lane >> 2);
        #pragma unroll
        for (int ni = 0; ni < 4; ni++) {
            const int col = col0 + wn + ni * 8 + (lane & 3) * 2;
            const float b0v = bias[col], b1v = bias[col + 1];
            float2 v0, v1;
            v0.x = acc[mi][ni][0] + b0v;
            v0.y = acc[mi][ni][1] + b1v;
            v1.x = acc[mi][ni][2] + b0v;
            v1.y = acc[mi][ni][3] + b1v;
            if (RELU) {
                v0.x = fmaxf(v0.x, 0.f); v0.y = fmaxf(v0.y, 0.f);
                v1.x = fmaxf(v1.x, 0.f); v1.y = fmaxf(v1.y, 0.f);
            }
            *reinterpret_cast<float2*>(C + (size_t)row * N + col)       = v0;
            *reinterpret_cast<float2*>(C + (size_t)(row + 8) * N + col) = v1;
        }
    }
}

// ---------------- attention (flash-lite): per (b,h), 64 q-rows / block ----
__global__ __launch_bounds__(256) void attn_kernel(
    const float* __restrict__ Q, const float* __restrict__ K,
    const float* __restrict__ V, float* __restrict__ O, int causal)
{
    __shared__ float Qs[64][65];
    __shared__ float Ks[32][65];
    __shared__ float Vs[32][65];
    __shared__ float Ps[64][33];

    const int tid = threadIdx.x;
    const int tx  = tid & 15;
    const int ty  = tid >> 4;
    const int b   = blockIdx.x >> 4;
    const int h   = blockIdx.x & 15;
    const int q0  = blockIdx.y * 64;

    const size_t base = ((size_t)b * 1024) * D + (size_t)h * 64;
    const float* Qb = Q + base + (size_t)q0 * D;

    for (int i = tid; i < 64 * 64; i += 256) {
        const int r = i >> 6, c = i & 63;
        Qs[r][c] = Qb[(size_t)r * D + c];
    }

    float mx[4], lsum[4], acc[4][4];
    #pragma unroll
    for (int i = 0; i < 4; i++) {
        mx[i] = -1e30f; lsum[i] = 0.f;
        #pragma unroll
        for (int j = 0; j < 4; j++) acc[i][j] = 0.f;
    }

    const int nkt = causal ? (q0 + 64) / 32 : 32;
    for (int jt = 0; jt < nkt; jt++) {
        const int j0 = jt * 32;
        const float* Kb = K + base + (size_t)j0 * D;
        const float* Vb = V + base + (size_t)j0 * D;
        for (int i = tid; i < 32 * 64; i += 256) {
            const int r = i >> 6, c = i & 63;
            Ks[r][c] = Kb[(size_t)r * D + c];
            Vs[r][c] = Vb[(size_t)r * D + c];
        }
        __syncthreads();

        float s[4][2];
        #pragma unroll
        for (int i = 0; i < 4; i++) { s[i][0] = 0.f; s[i][1] = 0.f; }
        #pragma unroll
        for (int kk = 0; kk < 64; kk++) {
            float qr[4];
            #pragma unroll
            for (int i = 0; i < 4; i++) qr[i] = Qs[4 * ty + i][kk];
            const float k0v = Ks[2 * tx + 0][kk];
            const float k1v = Ks[2 * tx + 1][kk];
            #pragma unroll
            for (int i = 0; i < 4; i++) {
                s[i][0] = fmaf(qr[i], k0v, s[i][0]);
                s[i][1] = fmaf(qr[i], k1v, s[i][1]);
            }
        }

        float fac[4];
        #pragma unroll
        for (int i = 0; i < 4; i++) {
            s[i][0] *= 0.125f;
            s[i][1] *= 0.125f;
            if (causal) {
                const int gq = q0 + 4 * ty + i;
                if (j0 + 2 * tx + 0 > gq) s[i][0] = -1e30f;
                if (j0 + 2 * tx + 1 > gq) s[i][1] = -1e30f;
            }
            float m = fmaxf(s[i][0], s[i][1]);
            #pragma unroll
            for (int o = 8; o > 0; o >>= 1)
                m = fmaxf(m, __shfl_xor_sync(0xffffffffu, m, o));
            const float mn = fmaxf(mx[i], m);
            fac[i] = __expf(mx[i] - mn);
            const float p0 = __expf(s[i][0] - mn);
            const float p1 = __expf(s[i][1] - mn);
            Ps[4 * ty + i][2 * tx + 0] = p0;
            Ps[4 * ty + i][2 * tx + 1] = p1;
            float rs = p0 + p1;
            #pragma unroll
            for (int o = 8; o > 0; o >>= 1)
                rs += __shfl_xor_sync(0xffffffffu, rs, o);
            lsum[i] = lsum[i] * fac[i] + rs;
            mx[i] = mn;
        }
        __syncthreads();

        #pragma unroll
        for (int i = 0; i < 4; i++)
            #pragma unroll
            for (int j = 0; j < 4; j++) acc[i][j] *= fac[i];

        #pragma unroll 8
        for (int jj = 0; jj < 32; jj++) {
            float pv[4], vv[4];
            #pragma unroll
            for (int i = 0; i < 4; i++) pv[i] = Ps[4 * ty + i][jj];
            #pragma unroll
            for (int j = 0; j < 4; j++) vv[j] = Vs[jj][4 * tx + j];
            #pragma unroll
            for (int i = 0; i < 4; i++)
                #pragma unroll
                for (int j = 0; j < 4; j++)
                    acc[i][j] = fmaf(pv[i], vv[j], acc[i][j]);
        }
        __syncthreads();
    }

    float* Ob = O + base + (size_t)q0 * D;
    #pragma unroll
    for (int i = 0; i < 4; i++) {
        const float inv = 1.f / lsum[i];
        #pragma unroll
        for (int j = 0; j < 4; j++)
            Ob[(size_t)(4 * ty + i) * D + 4 * tx + j] = acc[i][j] * inv;
    }
}

// ---------------- residual add + LayerNorm (one row per block) -------------
__device__ __forceinline__ float block_sum_256(float v, float* red)
{
    #pragma unroll
    for (int o = 16; o > 0; o >>= 1) v += __shfl_xor_sync(0xffffffffu, v, o);
    const int w = threadIdx.x >> 5;
    if ((threadIdx.x & 31) == 0) red[w] = v;
    __syncthreads();
    v = red[threadIdx.x & 7];
    #pragma unroll
    for (int o = 4; o > 0; o >>= 1) v += __shfl_xor_sync(0xffffffffu, v, o);
    __syncthreads();
    return v;
}

__global__ __launch_bounds__(256) void ln_kernel(
    const float* __restrict__ X, const float* __restrict__ Y,
    const float* __restrict__ g, const float* __restrict__ be,
    float* __restrict__ out)
{
    __shared__ float sm[D];
    __shared__ float red[8];
    const int row = blockIdx.x;
    const int tid = threadIdx.x;
    const float* x = X + (size_t)row * D;
    const float* y = Y + (size_t)row * D;

    float local = 0.f;
    #pragma unroll
    for (int i = tid; i < D; i += 256) {
        const float v = x[i] + y[i];
        sm[i] = v;
        local += v;
    }
    const float mean = block_sum_256(local, red) * (1.f / D);

    float lv = 0.f;
    #pragma unroll
    for (int i = tid; i < D; i += 256) {
        const float d = sm[i] - mean;
        lv += d * d;
    }
    const float var = block_sum_256(lv, red) * (1.f / D);
    const float rstd = rsqrtf(var + 1e-3f);

    #pragma unroll
    for (int i = tid; i < D; i += 256)
        out[(size_t)row * D + i] = (sm[i] - mean) * rstd * g[i] + be[i];
}

// ---------------- host orchestration ---------------------------------------
extern "C" void kernel_launch(void* const* d_in, const int* in_sizes, int n_in,
                              void* d_out, int out_size)
{
    const float* x   = (const float*)d_in[0];
    const float* enc = (const float*)d_in[1];

    const float *wq1, *bq1, *wk1, *bk1, *wv1, *bv1, *wo1, *bo1;
    const float *wq2, *bq2, *wk2, *bk2, *wv2, *bv2, *wo2, *bo2;
    const float *wff1, *bff1, *wff2, *bff2;
    const float *g1, *be1, *g2, *be2, *g3, *be3;

    if (in_sizes[3] == 1024) {
        wq1 = (const float*)d_in[2];  bq1 = (const float*)d_in[3];
        wk1 = (const float*)d_in[4];  bk1 = (const float*)d_in[5];
        wv1 = (const float*)d_in[6];  bv1 = (const float*)d_in[7];
        wo1 = (const float*)d_in[8];  bo1 = (const float*)d_in[9];
        wq2 = (const float*)d_in[10]; bq2 = (const float*)d_in[11];
        wk2 = (const float*)d_in[12]; bk2 = (const float*)d_in[13];
        wv2 = (const float*)d_in[14]; bv2 = (const float*)d_in[15];
        wo2 = (const float*)d_in[16]; bo2 = (const float*)d_in[17];
    } else {
        wq1 = (const float*)d_in[2];  wk1 = (const float*)d_in[3];
        wv1 = (const float*)d_in[4];  wo1 = (const float*)d_in[5];
        bq1 = (const float*)d_in[6];  bk1 = (const float*)d_in[7];
        bv1 = (const float*)d_in[8];  bo1 = (const float*)d_in[9];
        wq2 = (const float*)d_in[10]; wk2 = (const float*)d_in[11];
        wv2 = (const float*)d_in[12]; wo2 = (const float*)d_in[13];
        bq2 = (const float*)d_in[14]; bk2 = (const float*)d_in[15];
        bv2 = (const float*)d_in[16]; bo2 = (const float*)d_in[17];
    }
    wff1 = (const float*)d_in[18]; bff1 = (const float*)d_in[19];
    wff2 = (const float*)d_in[20]; bff2 = (const float*)d_in[21];
    g1 = (const float*)d_in[22]; be1 = (const float*)d_in[23];
    g2 = (const float*)d_in[24]; be2 = (const float*)d_in[25];
    g3 = (const float*)d_in[26]; be3 = (const float*)d_in[27];

    float *q, *k, *v, *ctx, *t1, *o1, *o2, *ff;
    cudaGetSymbolAddress((void**)&q,   g_q);
    cudaGetSymbolAddress((void**)&k,   g_k);
    cudaGetSymbolAddress((void**)&v,   g_v);
    cudaGetSymbolAddress((void**)&ctx, g_ctx);
    cudaGetSymbolAddress((void**)&t1,  g_t1);
    cudaGetSymbolAddress((void**)&o1,  g_o1);
    cudaGetSymbolAddress((void**)&o2,  g_o2);
    cudaGetSymbolAddress((void**)&ff,  g_ff);

    uint16_t *x3, *enc3, *o13, *o23, *ctx3, *ff3, *w3, *wf13, *wf23;
    cudaGetSymbolAddress((void**)&x3,   g_x3);
    cudaGetSymbolAddress((void**)&enc3, g_enc3);
    cudaGetSymbolAddress((void**)&o13,  g_o13);
    cudaGetSymbolAddress((void**)&o23,  g_o23);
    cudaGetSymbolAddress((void**)&ctx3, g_ctx3);
    cudaGetSymbolAddress((void**)&ff3,  g_ff3);
    cudaGetSymbolAddress((void**)&w3,   g_w3);
    cudaGetSymbolAddress((void**)&wf13, g_wf13);
    cudaGetSymbolAddress((void**)&wf23, g_wf23);

    cudaFuncSetAttribute(bf16s_gemm_kernel<false>,
        cudaFuncAttributeMaxDynamicSharedMemorySize, GEMM_SMEM_BYTES);
    cudaFuncSetAttribute(bf16s_gemm_kernel<true>,
        cudaFuncAttributeMaxDynamicSharedMemorySize, GEMM_SMEM_BYTES);

    const dim3 gD(D / 128, BS / 128);       // N=1024 GEMMs
    const dim3 gF1(DFF / 128, BS / 128);    // N=4096 GEMM
    const dim3 gAttn(64, 16);               // (B*H, S/64)
    const int SM = GEMM_SMEM_BYTES;

    const int T4_DD  = D * D / 4;           // weight D x D        (float4 count)
    const int T4_ACT = BS * D / 4;          // activation BS x D
    const int T4_FF  = BS * DFF / 4;        // activation BS x DFF
    const int T4_W1  = D * DFF / 4;         // wff1 [D, DFF]
    const int T4_W2  = DFF * D / 4;         // wff2 [DFF, D]

    // ---- weight splits (B-side) ----
    const float* wlist[8] = {wq1, wk1, wv1, wo1, wq2, wk2, wv2, wo2};
    for (int i = 0; i < 8; i++)
        split_b_kernel<<<T4_DD / 256, 256>>>(wlist[i], w3 + (size_t)i * 3 * D * D,
                                             D, D, T4_DD);
    split_b_kernel<<<T4_W1 / 256, 256>>>(wff1, wf13, D, DFF, T4_W1);
    split_b_kernel<<<T4_W2 / 256, 256>>>(wff2, wf23, DFF, D, T4_W2);

    // ---- activation splits for block 1 ----
    split_a_kernel<<<T4_ACT / 256, 256>>>(x,   x3,   D, T4_ACT);
    split_a_kernel<<<T4_ACT / 256, 256>>>(enc, enc3, D, T4_ACT);

    // ---- self-attention block (causal) ----
    bf16s_gemm_kernel<false><<<gD, 256, SM>>>(x3, w3 + 0 * (size_t)3 * D * D, bq1, q, BS, D, 3 * D);
    bf16s_gemm_kernel<false><<<gD, 256, SM>>>(x3, w3 + 1 * (size_t)3 * D * D, bk1, k, BS, D, 3 * D);
    bf16s_gemm_kernel<false><<<gD, 256, SM>>>(x3, w3 + 2 * (size_t)3 * D * D, bv1, v, BS, D, 3 * D);
    attn_kernel<<<gAttn, 256>>>(q, k, v, ctx, 1);
    split_a_kernel<<<T4_ACT / 256, 256>>>(ctx, ctx3, D, T4_ACT);
    bf16s_gemm_kernel<false><<<gD, 256, SM>>>(ctx3, w3 + 3 * (size_t)3 * D * D, bo1, t1, BS, D, 3 * D);
    ln_kernel<<<BS, 256>>>(x, t1, g1, be1, o1);

    // ---- cross-attention block ----
    split_a_kernel<<<T4_ACT / 256, 256>>>(o1, o13, D, T4_ACT);
    bf16s_gemm_kernel<false><<<gD, 256, SM>>>(o13,  w3 + 4 * (size_t)3 * D * D, bq2, q, BS, D, 3 * D);
    bf16s_gemm_kernel<false><<<gD, 256, SM>>>(enc3, w3 + 5 * (size_t)3 * D * D, bk2, k, BS, D, 3 * D);
    bf16s_gemm_kernel<false><<<gD, 256, SM>>>(enc3, w3 + 6 * (size_t)3 * D * D, bv2, v, BS, D, 3 * D);
    attn_kernel<<<gAttn, 256>>>(q, k, v, ctx, 0);
    split_a_kernel<<<T4_ACT / 256, 256>>>(ctx, ctx3, D, T4_ACT);
    bf16s_gemm_kernel<false><<<gD, 256, SM>>>(ctx3, w3 + 7 * (size_t)3 * D * D, bo2, t1, BS, D, 3 * D);
    ln_kernel<<<BS, 256>>>(o1, t1, g2, be2, o2);

    // ---- FFN block ----
    split_a_kernel<<<T4_ACT / 256, 256>>>(o2, o23, D, T4_ACT);
    bf16s_gemm_kernel<true ><<<gF1, 256, SM>>>(o23, wf13, bff1, ff, BS, DFF, 3 * D);
    split_a_kernel<<<T4_FF / 256, 256>>>(ff, ff3, DFF, T4_FF);
    bf16s_gemm_kernel<false><<<gD, 256, SM>>>(ff3, wf23, bff2, t1, BS, D, 3 * DFF);
    ln_kernel<<<BS, 256>>>(o2, t1, g3, be3, (float*)d_out);

    (void)n_in; (void)out_size;
}

// round 13
// speedup vs baseline: 2.6554x; 1.3850x over previous
#include <cuda_runtime.h>
#include <math.h>
#include <stdint.h>

// ---------------- scratch (device globals: allocation-free) ----------------
#define BS  4096          // B*S
#define D   1024
#define DFF 4096

__device__ float g_t1 [BS * D];
__device__ float g_o1 [BS * D];
__device__ float g_o2 [BS * D];

// split-bf16 buffers
__device__ uint16_t g_x3  [BS * 3 * D];     // [hi|lo|hi] A-format
__device__ uint16_t g_enc3[BS * 3 * D];
__device__ uint16_t g_o13 [BS * 3 * D];
__device__ uint16_t g_o23 [BS * 3 * D];
__device__ uint16_t g_ctx3[BS * 3 * D];
__device__ uint16_t g_ff3 [BS * 3 * DFF];
__device__ uint16_t g_q2  [BS * 2 * D];     // [hi|lo]
__device__ uint16_t g_k2  [BS * 2 * D];
__device__ uint16_t g_v2  [BS * 2 * D];
__device__ uint16_t g_w3  [8][3 * D * D];   // [hi;hi;lo] B-format
__device__ uint16_t g_wf13[3 * D * DFF];
__device__ uint16_t g_wf23[3 * DFF * D];

// ---------------- helpers ---------------------------------------------------
__device__ __forceinline__ uint32_t smem_u32(const void* p) {
    uint32_t a;
    asm("{ .reg .u64 t; cvta.to.shared.u64 t, %1; cvt.u32.u64 %0, t; }"
        : "=r"(a) : "l"(p));
    return a;
}

__device__ __forceinline__ uint32_t cvt2_bf16(float x1, float x0) {
    uint32_t r;
    asm("cvt.rn.bf16x2.f32 %0, %1, %2;" : "=r"(r) : "f"(x1), "f"(x0));
    return r;
}

__device__ __forceinline__ void split2(float x0, float x1,
                                       uint32_t& h, uint32_t& l) {
    h = cvt2_bf16(x1, x0);
    const float h0 = __uint_as_float(h << 16);
    const float h1 = __uint_as_float(h & 0xffff0000u);
    l = cvt2_bf16(x1 - h1, x0 - h0);
}

__device__ __forceinline__ void ldsm_x4(uint32_t* r, uint32_t addr) {
    asm volatile("ldmatrix.sync.aligned.m8n8.x4.shared.b16 {%0,%1,%2,%3}, [%4];"
                 : "=r"(r[0]), "=r"(r[1]), "=r"(r[2]), "=r"(r[3]) : "r"(addr));
}
__device__ __forceinline__ void ldsm_x4_t(uint32_t* r, uint32_t addr) {
    asm volatile("ldmatrix.sync.aligned.m8n8.x4.trans.shared.b16 {%0,%1,%2,%3}, [%4];"
                 : "=r"(r[0]), "=r"(r[1]), "=r"(r[2]), "=r"(r[3]) : "r"(addr));
}

__device__ __forceinline__ void mma_bf16(float* d, const uint32_t* a,
                                         const uint32_t* b) {
    asm volatile(
        "mma.sync.aligned.m16n8k16.row.col.f32.bf16.bf16.f32 "
        "{%0,%1,%2,%3}, {%4,%5,%6,%7}, {%8,%9}, {%0,%1,%2,%3};"
        : "+f"(d[0]), "+f"(d[1]), "+f"(d[2]), "+f"(d[3])
        : "r"(a[0]), "r"(a[1]), "r"(a[2]), "r"(a[3]), "r"(b[0]), "r"(b[1]));
}

__device__ __forceinline__ void cp16(uint32_t dst, const void* src) {
    asm volatile("cp.async.cg.shared.global [%0], [%1], 16;"
                 :: "r"(dst), "l"(src));
}
#define CP_COMMIT() asm volatile("cp.async.commit_group;")

// ---------------- split kernels (inputs only) -------------------------------
// A': out[m, k]=hi, out[m, K+k]=lo, out[m, 2K+k]=hi     (out is [M, 3K] bf16)
__global__ void split_a_kernel(const float* __restrict__ in,
                               uint16_t* __restrict__ out, int K, int total4)
{
    const int idx = blockIdx.x * blockDim.x + threadIdx.x;
    if (idx >= total4) return;
    const float4 v = reinterpret_cast<const float4*>(in)[idx];
    uint32_t h0, l0, h1, l1;
    split2(v.x, v.y, h0, l0);
    split2(v.z, v.w, h1, l1);
    const int e = idx * 4;
    const int m = e / K, k = e % K;
    uint16_t* rp = out + (size_t)m * 3 * K;
    const uint2 H = make_uint2(h0, h1), L = make_uint2(l0, l1);
    *reinterpret_cast<uint2*>(rp + k)         = H;
    *reinterpret_cast<uint2*>(rp + 2 * K + k) = H;
    *reinterpret_cast<uint2*>(rp + K + k)     = L;
}

// B': out[k, n]=hi, out[K+k, n]=hi, out[2K+k, n]=lo     (out is [3K, N] bf16)
__global__ void split_b_kernel(const float* __restrict__ in,
                               uint16_t* __restrict__ out, int K, int N,
                               int total4)
{
    const int idx = blockIdx.x * blockDim.x + threadIdx.x;
    if (idx >= total4) return;
    const float4 v = reinterpret_cast<const float4*>(in)[idx];
    uint32_t h0, l0, h1, l1;
    split2(v.x, v.y, h0, l0);
    split2(v.z, v.w, h1, l1);
    const int e = idx * 4;
    const int k = e / N, n = e % N;
    const uint2 H = make_uint2(h0, h1), L = make_uint2(l0, l1);
    *reinterpret_cast<uint2*>(out + (size_t)k * N + n)           = H;
    *reinterpret_cast<uint2*>(out + (size_t)(K + k) * N + n)     = H;
    *reinterpret_cast<uint2*>(out + (size_t)(2 * K + k) * N + n) = L;
}

// ---------------- bf16 GEMM: C = A'[M,K3] @ B'[K3,N] + bias (+ReLU) --------
// OM: 0 = f32 out, 2 = split2 bf16 out [hi|lo], 3 = split3 bf16 out [hi|lo|hi]
#define A_STG_B 10240                     // 128 * 80
#define B_STG_B 8704                      // 32 * 272
#define STG_B   (A_STG_B + B_STG_B)       // 18944
#define GEMM_SMEM_BYTES (3 * STG_B)       // 56832

template <bool RELU, int OM>
__global__ __launch_bounds__(256, 2) void bf16s_gemm_kernel(
    const uint16_t* __restrict__ A3, const uint16_t* __restrict__ B3,
    const float* __restrict__ bias, void* __restrict__ Cv,
    int M, int N, int K3)
{
    extern __shared__ char smem[];
    const uint32_t sb = smem_u32(smem);
    const int tid  = threadIdx.x;
    const int lane = tid & 31;
    const int wid  = tid >> 5;
    const int wm   = (wid >> 2) * 64;
    const int wn   = (wid & 3) * 32;
    const int row0 = blockIdx.y * 128;
    const int col0 = blockIdx.x * 128;
    const int NS   = K3 >> 5;

    const int a_r  = tid >> 2, a_sg = tid & 3;
    const int b_r  = tid >> 4, b_sg = tid & 15;

    float acc[4][4][4];
    #pragma unroll
    for (int mi = 0; mi < 4; mi++)
        #pragma unroll
        for (int ni = 0; ni < 4; ni++)
            #pragma unroll
            for (int r = 0; r < 4; r++) acc[mi][ni][r] = 0.f;

    #define ISSUE_STAGE(s) do {                                               \
        const uint32_t _b = sb + ((s) % 3) * STG_B;                           \
        const int _k0 = (s) * 32;                                             \
        cp16(_b + a_r * 80 + a_sg * 16,                                       \
             A3 + (size_t)(row0 + a_r) * K3 + _k0 + a_sg * 8);                \
        cp16(_b + (a_r + 64) * 80 + a_sg * 16,                                \
             A3 + (size_t)(row0 + a_r + 64) * K3 + _k0 + a_sg * 8);           \
        cp16(_b + A_STG_B + b_r * 272 + b_sg * 16,                            \
             B3 + (size_t)(_k0 + b_r) * N + col0 + b_sg * 8);                 \
        cp16(_b + A_STG_B + (b_r + 16) * 272 + b_sg * 16,                     \
             B3 + (size_t)(_k0 + b_r + 16) * N + col0 + b_sg * 8);            \
        CP_COMMIT();                                                          \
    } while (0)

    ISSUE_STAGE(0);
    ISSUE_STAGE(1);

    for (int s = 0; s < NS; s++) {
        if (s < NS - 1) asm volatile("cp.async.wait_group 1;" ::: "memory");
        else            asm volatile("cp.async.wait_group 0;" ::: "memory");
        __syncthreads();
        if (s + 2 < NS) ISSUE_STAGE(s + 2);

        const uint32_t base = sb + (s % 3) * STG_B;
        const uint32_t ab = base, bb = base + A_STG_B;

        #pragma unroll
        for (int ks = 0; ks < 2; ks++) {
            uint32_t a[4][4], bfr[2][4];
            #pragma unroll
            for (int mi = 0; mi < 4; mi++)
                ldsm_x4(a[mi], ab + (wm + (lane & 15) + mi * 16) * 80
                                  + ks * 32 + (lane >> 4) * 16);
            #pragma unroll
            for (int nj = 0; nj < 2; nj++)
                ldsm_x4_t(bfr[nj], bb + ((lane & 7) + ((lane >> 3) & 1) * 8
                                         + ks * 16) * 272
                                      + wn * 2 + (lane >> 4) * 16 + nj * 32);
            #pragma unroll
            for (int mi = 0; mi < 4; mi++)
                #pragma unroll
                for (int ni = 0; ni < 4; ni++)
                    mma_bf16(acc[mi][ni], a[mi], &bfr[ni >> 1][(ni & 1) * 2]);
        }
    }
    #undef ISSUE_STAGE

    // epilogue
    #pragma unroll
    for (int mi = 0; mi < 4; mi++) {
        const int row = row0 + wm + mi * 16 + (lane >> 2);
        #pragma unroll
        for (int ni = 0; ni < 4; ni++) {
            const int col = col0 + wn + ni * 8 + (lane & 3) * 2;
            const float b0v = bias[col], b1v = bias[col + 1];
            float v0 = acc[mi][ni][0] + b0v;
            float v1 = acc[mi][ni][1] + b1v;
            float v2 = acc[mi][ni][2] + b0v;
            float v3 = acc[mi][ni][3] + b1v;
            if (RELU) {
                v0 = fmaxf(v0, 0.f); v1 = fmaxf(v1, 0.f);
                v2 = fmaxf(v2, 0.f); v3 = fmaxf(v3, 0.f);
            }
            if (OM == 0) {
                float* C = (float*)Cv;
                *reinterpret_cast<float2*>(C + (size_t)row * N + col)
                    = make_float2(v0, v1);
                *reinterpret_cast<float2*>(C + (size_t)(row + 8) * N + col)
                    = make_float2(v2, v3);
            } else {
                uint32_t* Cw = (uint32_t*)Cv;
                const int p32 = (OM == 2) ? N : (3 * N) / 2;
                uint32_t hh, ll;
                split2(v0, v1, hh, ll);
                size_t i0 = (size_t)row * p32 + (col >> 1);
                Cw[i0] = hh; Cw[i0 + N / 2] = ll;
                if (OM == 3) Cw[i0 + N] = hh;
                split2(v2, v3, hh, ll);
                size_t i1 = (size_t)(row + 8) * p32 + (col >> 1);
                Cw[i1] = hh; Cw[i1 + N / 2] = ll;
                if (OM == 3) Cw[i1 + N] = hh;
            }
        }
    }
}

// ---------------- tensor-core flash attention -------------------------------
// Q smem [64][200] bf16 [hi|lo|hi], K stage [64][200] [hi|hi|lo],
// V stage [64][136] [hi(64)|lo(64)].  2-stage cp.async ring on K/V.
// 128 threads: warp w = q-rows [16w, 16w+16).  Output: ctx3 split3 bf16.
#define ATT_SMEM 111616    // 25600 + 2*43008

__global__ __launch_bounds__(128) void attn_tc_kernel(
    const uint16_t* __restrict__ Q2, const uint16_t* __restrict__ K2,
    const uint16_t* __restrict__ V2, uint16_t* __restrict__ C3, int causal)
{
    extern __shared__ char smem[];
    const uint32_t sb = smem_u32(smem);
    const int tid  = threadIdx.x;
    const int lane = tid & 31;
    const int w    = tid >> 5;
    const int b    = blockIdx.x >> 4;
    const int h    = blockIdx.x & 15;
    const int q0   = blockIdx.y * 64;

    const uint32_t Qb = sb;
    const uint32_t KST0 = sb + 25600;
    const int hc = h * 64;
    const size_t qrow0 = (size_t)b * 1024 + q0;
    const int nkt = causal ? (q0 >> 6) + 1 : 16;

    #define ISSUE_TILE(j, st) do {                                            \
        const size_t _kr = (size_t)b * 1024 + (size_t)(j) * 64;               \
        const uint32_t _kb = KST0 + (st) * 43008;                             \
        for (int i = tid; i < 1536; i += 128) {                               \
            const int r = i / 24, t = i % 24, seg = t >> 3, c = t & 7;        \
            const int sc = (seg == 2 ? 1024 + hc : hc) + c * 8;               \
            cp16(_kb + r * 400 + seg * 128 + c * 16,                          \
                 K2 + (_kr + r) * 2048 + sc);                                 \
        }                                                                     \
        for (int i = tid; i < 1024; i += 128) {                               \
            const int r = i >> 4, t = i & 15, seg = t >> 3, c = t & 7;        \
            const int sc = (seg ? 1024 + hc : hc) + c * 8;                    \
            cp16(_kb + 25600 + r * 272 + seg * 128 + c * 16,                  \
                 V2 + (_kr + r) * 2048 + sc);                                 \
        }                                                                     \
        CP_COMMIT();                                                          \
    } while (0)

    // Q load (group with tile 0)
    for (int i = tid; i < 1536; i += 128) {
        const int r = i / 24, t = i % 24, seg = t >> 3, c = t & 7;
        const int sc = (seg == 1 ? 1024 + hc : hc) + c * 8;   // hi|lo|hi
        cp16(Qb + r * 400 + seg * 128 + c * 16, Q2 + (qrow0 + r) * 2048 + sc);
    }
    ISSUE_TILE(0, 0);
    if (nkt > 1) ISSUE_TILE(1, 1);

    float oacc[8][4];
    #pragma unroll
    for (int t = 0; t < 8; t++)
        #pragma unroll
        for (int r = 0; r < 4; r++) oacc[t][r] = 0.f;
    float m0 = -1e30f, m1 = -1e30f, l0 = 0.f, l1 = 0.f;

    const int qr0 = q0 + w * 16 + (lane >> 2);     // row0; row1 = +8

    for (int s = 0; s < nkt; s++) {
        if (s + 1 < nkt) asm volatile("cp.async.wait_group 1;" ::: "memory");
        else             asm volatile("cp.async.wait_group 0;" ::: "memory");
        __syncthreads();
        const uint32_t Kb = KST0 + (s & 1) * 43008;
        const uint32_t Vb = Kb + 25600;

        // ---- S = (Q K^T) * 0.125, split 3-term over k'=192 ----
        float sc[8][4];
        #pragma unroll
        for (int t = 0; t < 8; t++)
            #pragma unroll
            for (int r = 0; r < 4; r++) sc[t][r] = 0.f;

        #pragma unroll
        for (int ks = 0; ks < 12; ks++) {
            uint32_t aq[4];
            ldsm_x4(aq, Qb + (w * 16 + (lane & 15)) * 400
                          + ks * 32 + (lane >> 4) * 16);
            #pragma unroll
            for (int nt4 = 0; nt4 < 4; nt4++) {
                uint32_t bk[4];
                ldsm_x4(bk, Kb + (nt4 * 16 + ((lane >> 4) & 1) * 8
                                  + (lane & 7)) * 400
                              + ks * 32 + ((lane >> 3) & 1) * 16);
                mma_bf16(sc[nt4 * 2], aq, &bk[0]);
                mma_bf16(sc[nt4 * 2 + 1], aq, &bk[2]);
            }
        }

        #pragma unroll
        for (int t = 0; t < 8; t++)
            #pragma unroll
            for (int r = 0; r < 4; r++) sc[t][r] *= 0.125f;

        if (causal && s == nkt - 1) {   // diagonal tile
            #pragma unroll
            for (int t = 0; t < 8; t++) {
                const int k0e = s * 64 + t * 8 + (lane & 3) * 2;
                if (k0e > qr0)         sc[t][0] = -1e30f;
                if (k0e + 1 > qr0)     sc[t][1] = -1e30f;
                if (k0e > qr0 + 8)     sc[t][2] = -1e30f;
                if (k0e + 1 > qr0 + 8) sc[t][3] = -1e30f;
            }
        }

        // ---- online softmax ----
        float mx0 = -1e30f, mx1 = -1e30f;
        #pragma unroll
        for (int t = 0; t < 8; t++) {
            mx0 = fmaxf(mx0, fmaxf(sc[t][0], sc[t][1]));
            mx1 = fmaxf(mx1, fmaxf(sc[t][2], sc[t][3]));
        }
        mx0 = fmaxf(mx0, __shfl_xor_sync(0xffffffffu, mx0, 1));
        mx0 = fmaxf(mx0, __shfl_xor_sync(0xffffffffu, mx0, 2));
        mx1 = fmaxf(mx1, __shfl_xor_sync(0xffffffffu, mx1, 1));
        mx1 = fmaxf(mx1, __shfl_xor_sync(0xffffffffu, mx1, 2));
        const float mn0 = fmaxf(m0, mx0), mn1 = fmaxf(m1, mx1);
        const float f0 = __expf(m0 - mn0), f1 = __expf(m1 - mn1);
        m0 = mn0; m1 = mn1;

        float s0 = 0.f, s1 = 0.f;
        #pragma unroll
        for (int t = 0; t < 8; t++) {
            sc[t][0] = __expf(sc[t][0] - mn0);
            sc[t][1] = __expf(sc[t][1] - mn0);
            sc[t][2] = __expf(sc[t][2] - mn1);
            sc[t][3] = __expf(sc[t][3] - mn1);
            s0 += sc[t][0] + sc[t][1];
            s1 += sc[t][2] + sc[t][3];
        }
        s0 += __shfl_xor_sync(0xffffffffu, s0, 1);
        s0 += __shfl_xor_sync(0xffffffffu, s0, 2);
        s1 += __shfl_xor_sync(0xffffffffu, s1, 1);
        s1 += __shfl_xor_sync(0xffffffffu, s1, 2);
        l0 = l0 * f0 + s0;
        l1 = l1 * f1 + s1;
        #pragma unroll
        for (int t = 0; t < 8; t++) {
            oacc[t][0] *= f0; oacc[t][1] *= f0;
            oacc[t][2] *= f1; oacc[t][3] *= f1;
        }

        // ---- O += P V  (Ph*Vh + Pl*Vh + Ph*Vl) ----
        #pragma unroll
        for (int ks = 0; ks < 4; ks++) {
            uint32_t ah[4], al[4];
            split2(sc[2 * ks][0],     sc[2 * ks][1],     ah[0], al[0]);
            split2(sc[2 * ks][2],     sc[2 * ks][3],     ah[1], al[1]);
            split2(sc[2 * ks + 1][0], sc[2 * ks + 1][1], ah[2], al[2]);
            split2(sc[2 * ks + 1][2], sc[2 * ks + 1][3], ah[3], al[3]);
            #pragma unroll
            for (int dt4 = 0; dt4 < 4; dt4++) {
                const uint32_t va = Vb + ((lane & 7) + ((lane >> 3) & 1) * 8
                                          + ks * 16) * 272
                                       + dt4 * 32 + (lane >> 4) * 16;
                uint32_t bh[4], bl[4];
                ldsm_x4_t(bh, va);
                ldsm_x4_t(bl, va + 128);
                mma_bf16(oacc[dt4 * 2],     ah, &bh[0]);
                mma_bf16(oacc[dt4 * 2 + 1], ah, &bh[2]);
                mma_bf16(oacc[dt4 * 2],     al, &bh[0]);
                mma_bf16(oacc[dt4 * 2 + 1], al, &bh[2]);
                mma_bf16(oacc[dt4 * 2],     ah, &bl[0]);
                mma_bf16(oacc[dt4 * 2 + 1], ah, &bl[2]);
            }
        }
        __syncthreads();
        if (s + 2 < nkt) ISSUE_TILE(s + 2, s & 1);
    }
    #undef ISSUE_TILE

    // ---- epilogue: O/l -> ctx3 split3 [hi|lo|hi] ----
    const float i0 = 1.f / l0, i1 = 1.f / l1;
    uint32_t* Cw = (uint32_t*)C3;
    const size_t gr0 = ((size_t)b * 1024 + qr0) * 1536;
    const size_t gr1 = gr0 + (size_t)8 * 1536;
    #pragma unroll
    for (int dt = 0; dt < 8; dt++) {
        const int cu = (hc + dt * 8 + (lane & 3) * 2) >> 1;
        uint32_t hh, ll;
        split2(oacc[dt][0] * i0, oacc[dt][1] * i0, hh, ll);
        Cw[gr0 + cu] = hh; Cw[gr0 + 512 + cu] = ll; Cw[gr0 + 1024 + cu] = hh;
        split2(oacc[dt][2] * i1, oacc[dt][3] * i1, hh, ll);
        Cw[gr1 + cu] = hh; Cw[gr1 + 512 + cu] = ll; Cw[gr1 + 1024 + cu] = hh;
    }
}

// ---------------- residual add + LayerNorm (+ optional split3 out) ---------
__device__ __forceinline__ float block_sum_256(float v, float* red)
{
    #pragma unroll
    for (int o = 16; o > 0; o >>= 1) v += __shfl_xor_sync(0xffffffffu, v, o);
    const int w = threadIdx.x >> 5;
    if ((threadIdx.x & 31) == 0) red[w] = v;
    __syncthreads();
    v = red[threadIdx.x & 7];
    #pragma unroll
    for (int o = 4; o > 0; o >>= 1) v += __shfl_xor_sync(0xffffffffu, v, o);
    __syncthreads();
    return v;
}

__global__ __launch_bounds__(256) void ln_kernel(
    const float* __restrict__ X, const float* __restrict__ Y,
    const float* __restrict__ g, const float* __restrict__ be,
    float* __restrict__ out, uint16_t* __restrict__ out3)
{
    __shared__ float sm[D];
    __shared__ float red[8];
    const int row = blockIdx.x;
    const int tid = threadIdx.x;
    const float* x = X + (size_t)row * D;
    const float* y = Y + (size_t)row * D;

    float local = 0.f;
    #pragma unroll
    for (int i = tid; i < D; i += 256) {
        const float v = x[i] + y[i];
        sm[i] = v;
        local += v;
    }
    const float mean = block_sum_256(local, red) * (1.f / D);

    float lv = 0.f;
    #pragma unroll
    for (int i = tid; i < D; i += 256) {
        const float d = sm[i] - mean;
        lv += d * d;
    }
    const float var = block_sum_256(lv, red) * (1.f / D);
    const float rstd = rsqrtf(var + 1e-3f);

    if (out3) {
        uint16_t* r3 = out3 + (size_t)row * 3 * D;
        #pragma unroll
        for (int i = tid; i < D; i += 256) {
            const float val = (sm[i] - mean) * rstd * g[i] + be[i];
            out[(size_t)row * D + i] = val;
            uint32_t hh, ll;
            split2(val, 0.f, hh, ll);
            r3[i]         = (uint16_t)hh;
            r3[D + i]     = (uint16_t)ll;
            r3[2 * D + i] = (uint16_t)hh;
        }
    } else {
        #pragma unroll
        for (int i = tid; i < D; i += 256)
            out[(size_t)row * D + i] = (sm[i] - mean) * rstd * g[i] + be[i];
    }
}

// ---------------- host orchestration ---------------------------------------
extern "C" void kernel_launch(void* const* d_in, const int* in_sizes, int n_in,
                              void* d_out, int out_size)
{
    const float* x   = (const float*)d_in[0];
    const float* enc = (const float*)d_in[1];

    const float *wq1, *bq1, *wk1, *bk1, *wv1, *bv1, *wo1, *bo1;
    const float *wq2, *bq2, *wk2, *bk2, *wv2, *bv2, *wo2, *bo2;
    const float *wff1, *bff1, *wff2, *bff2;
    const float *g1, *be1, *g2, *be2, *g3, *be3;

    if (in_sizes[3] == 1024) {
        wq1 = (const float*)d_in[2];  bq1 = (const float*)d_in[3];
        wk1 = (const float*)d_in[4];  bk1 = (const float*)d_in[5];
        wv1 = (const float*)d_in[6];  bv1 = (const float*)d_in[7];
        wo1 = (const float*)d_in[8];  bo1 = (const float*)d_in[9];
        wq2 = (const float*)d_in[10]; bq2 = (const float*)d_in[11];
        wk2 = (const float*)d_in[12]; bk2 = (const float*)d_in[13];
        wv2 = (const float*)d_in[14]; bv2 = (const float*)d_in[15];
        wo2 = (const float*)d_in[16]; bo2 = (const float*)d_in[17];
    } else {
        wq1 = (const float*)d_in[2];  wk1 = (const float*)d_in[3];
        wv1 = (const float*)d_in[4];  wo1 = (const float*)d_in[5];
        bq1 = (const float*)d_in[6];  bk1 = (const float*)d_in[7];
        bv1 = (const float*)d_in[8];  bo1 = (const float*)d_in[9];
        wq2 = (const float*)d_in[10]; wk2 = (const float*)d_in[11];
        wv2 = (const float*)d_in[12]; wo2 = (const float*)d_in[13];
        bq2 = (const float*)d_in[14]; bk2 = (const float*)d_in[15];
        bv2 = (const float*)d_in[16]; bo2 = (const float*)d_in[17];
    }
    wff1 = (const float*)d_in[18]; bff1 = (const float*)d_in[19];
    wff2 = (const float*)d_in[20]; bff2 = (const float*)d_in[21];
    g1 = (const float*)d_in[22]; be1 = (const float*)d_in[23];
    g2 = (const float*)d_in[24]; be2 = (const float*)d_in[25];
    g3 = (const float*)d_in[26]; be3 = (const float*)d_in[27];

    float *t1, *o1, *o2;
    cudaGetSymbolAddress((void**)&t1, g_t1);
    cudaGetSymbolAddress((void**)&o1, g_o1);
    cudaGetSymbolAddress((void**)&o2, g_o2);

    uint16_t *x3, *enc3, *o13, *o23, *ctx3, *ff3, *q2, *k2, *v2;
    uint16_t *w3, *wf13, *wf23;
    cudaGetSymbolAddress((void**)&x3,   g_x3);
    cudaGetSymbolAddress((void**)&enc3, g_enc3);
    cudaGetSymbolAddress((void**)&o13,  g_o13);
    cudaGetSymbolAddress((void**)&o23,  g_o23);
    cudaGetSymbolAddress((void**)&ctx3, g_ctx3);
    cudaGetSymbolAddress((void**)&ff3,  g_ff3);
    cudaGetSymbolAddress((void**)&q2,   g_q2);
    cudaGetSymbolAddress((void**)&k2,   g_k2);
    cudaGetSymbolAddress((void**)&v2,   g_v2);
    cudaGetSymbolAddress((void**)&w3,   g_w3);
    cudaGetSymbolAddress((void**)&wf13, g_wf13);
    cudaGetSymbolAddress((void**)&wf23, g_wf23);

    cudaFuncSetAttribute(bf16s_gemm_kernel<false, 0>,
        cudaFuncAttributeMaxDynamicSharedMemorySize, GEMM_SMEM_BYTES);
    cudaFuncSetAttribute(bf16s_gemm_kernel<false, 2>,
        cudaFuncAttributeMaxDynamicSharedMemorySize, GEMM_SMEM_BYTES);
    cudaFuncSetAttribute(bf16s_gemm_kernel<true, 3>,
        cudaFuncAttributeMaxDynamicSharedMemorySize, GEMM_SMEM_BYTES);
    cudaFuncSetAttribute(attn_tc_kernel,
        cudaFuncAttributeMaxDynamicSharedMemorySize, ATT_SMEM);

    const dim3 gD(D / 128, BS / 128);
    const dim3 gF1(DFF / 128, BS / 128);
    const dim3 gAttn(64, 16);
    const int SM = GEMM_SMEM_BYTES;

    const int T4_DD  = D * D / 4;
    const int T4_ACT = BS * D / 4;
    const int T4_W1  = D * DFF / 4;
    const int T4_W2  = DFF * D / 4;

    // weight splits (B-side)
    const float* wlist[8] = {wq1, wk1, wv1, wo1, wq2, wk2, wv2, wo2};
    for (int i = 0; i < 8; i++)
        split_b_kernel<<<T4_DD / 256, 256>>>(wlist[i], w3 + (size_t)i * 3 * D * D,
                                             D, D, T4_DD);
    split_b_kernel<<<T4_W1 / 256, 256>>>(wff1, wf13, D, DFF, T4_W1);
    split_b_kernel<<<T4_W2 / 256, 256>>>(wff2, wf23, DFF, D, T4_W2);

    // input activation splits
    split_a_kernel<<<T4_ACT / 256, 256>>>(x,   x3,   D, T4_ACT);
    split_a_kernel<<<T4_ACT / 256, 256>>>(enc, enc3, D, T4_ACT);

    // ---- self-attention block (causal) ----
    bf16s_gemm_kernel<false, 2><<<gD, 256, SM>>>(x3, w3 + 0 * (size_t)3 * D * D, bq1, q2, BS, D, 3 * D);
    bf16s_gemm_kernel<false, 2><<<gD, 256, SM>>>(x3, w3 + 1 * (size_t)3 * D * D, bk1, k2, BS, D, 3 * D);
    bf16s_gemm_kernel<false, 2><<<gD, 256, SM>>>(x3, w3 + 2 * (size_t)3 * D * D, bv1, v2, BS, D, 3 * D);
    attn_tc_kernel<<<gAttn, 128, ATT_SMEM>>>(q2, k2, v2, ctx3, 1);
    bf16s_gemm_kernel<false, 0><<<gD, 256, SM>>>(ctx3, w3 + 3 * (size_t)3 * D * D, bo1, t1, BS, D, 3 * D);
    ln_kernel<<<BS, 256>>>(x, t1, g1, be1, o1, o13);

    // ---- cross-attention block ----
    bf16s_gemm_kernel<false, 2><<<gD, 256, SM>>>(o13,  w3 + 4 * (size_t)3 * D * D, bq2, q2, BS, D, 3 * D);
    bf16s_gemm_kernel<false, 2><<<gD, 256, SM>>>(enc3, w3 + 5 * (size_t)3 * D * D, bk2, k2, BS, D, 3 * D);
    bf16s_gemm_kernel<false, 2><<<gD, 256, SM>>>(enc3, w3 + 6 * (size_t)3 * D * D, bv2, v2, BS, D, 3 * D);
    attn_tc_kernel<<<gAttn, 128, ATT_SMEM>>>(q2, k2, v2, ctx3, 0);
    bf16s_gemm_kernel<false, 0><<<gD, 256, SM>>>(ctx3, w3 + 7 * (size_t)3 * D * D, bo2, t1, BS, D, 3 * D);
    ln_kernel<<<BS, 256>>>(o1, t1, g2, be2, o2, o23);

    // ---- FFN block ----
    bf16s_gemm_kernel<true, 3><<<gF1, 256, SM>>>(o23, wf13, bff1, ff3, BS, DFF, 3 * D);
    bf16s_gemm_kernel<false, 0><<<gD, 256, SM>>>(ff3, wf23, bff2, t1, BS, D, 3 * DFF);
    ln_kernel<<<BS, 256>>>(o2, t1, g3, be3, (float*)d_out, nullptr);

    (void)n_in; (void)out_size;
}